// round 16
// baseline (speedup 1.0000x reference)
#include <cuda_runtime.h>
#include <cuda_fp16.h>
#include <cstdint>
#include <math.h>

// Problem constants
#define BB 4
#define TT 2048
#define CC 1024
#define NH 16
#define HSZ 64
#define MROWS (BB*TT)        // 8192
#define THREECC (3*CC)       // 3072
#define KD 1024

// ---------------------------------------------------------------------------
// Global scratch (device globals: allocation-free). fp16 hi planes only.
// ---------------------------------------------------------------------------
__device__ __half g_qkvh[(size_t)MROWS * THREECC];  // qkv
__device__ __half g_xh[(size_t)MROWS * CC];         // x [M][K]
__device__ __half g_wah[(size_t)THREECC * CC];      // w_attn^T [N][K]
__device__ __half g_wph[(size_t)CC * CC];           // w_proj^T [N][K]
__device__ __half g_ah[(size_t)MROWS * CC];         // attn out

// ---------------------------------------------------------------------------
// Helpers
// ---------------------------------------------------------------------------
__device__ __forceinline__ uint32_t smem_u32(const void* p) {
    uint32_t a;
    asm("{ .reg .u64 t; cvta.to.shared.u64 t, %1; cvt.u32.u64 %0, t; }"
        : "=r"(a) : "l"(p));
    return a;
}

__device__ __forceinline__ void cp16(uint32_t dst, const void* src) {
    asm volatile("cp.async.cg.shared.global [%0], [%1], 16;"
                 :: "r"(dst), "l"(src));
}
#define CP_COMMIT() asm volatile("cp.async.commit_group;" ::: "memory")
#define CP_WAIT(n)  asm volatile("cp.async.wait_group %0;" :: "n"(n) : "memory")

__device__ __forceinline__ void ldm_x4(uint32_t* r, uint32_t addr) {
    asm volatile("ldmatrix.sync.aligned.m8n8.x4.shared.b16 {%0,%1,%2,%3}, [%4];"
                 : "=r"(r[0]), "=r"(r[1]), "=r"(r[2]), "=r"(r[3]) : "r"(addr));
}
__device__ __forceinline__ void ldm_x4t(uint32_t* r, uint32_t addr) {
    asm volatile("ldmatrix.sync.aligned.m8n8.x4.trans.shared.b16 {%0,%1,%2,%3}, [%4];"
                 : "=r"(r[0]), "=r"(r[1]), "=r"(r[2]), "=r"(r[3]) : "r"(addr));
}

#define MMA_F16(acc, a, b0, b1)                                               \
    asm volatile(                                                             \
        "mma.sync.aligned.m16n8k16.row.col.f32.f16.f16.f32 "                  \
        "{%0,%1,%2,%3},{%4,%5,%6,%7},{%8,%9},{%0,%1,%2,%3};"                  \
        : "+f"((acc)[0]), "+f"((acc)[1]), "+f"((acc)[2]), "+f"((acc)[3])      \
        : "r"((a)[0]), "r"((a)[1]), "r"((a)[2]), "r"((a)[3]),                 \
          "r"(b0), "r"(b1))

__device__ __forceinline__ float ex2f(float x) {
    float y;
    asm("ex2.approx.f32 %0, %1;" : "=f"(y) : "f"(x));
    return y;
}

__device__ __forceinline__ uint32_t ex2_h2(uint32_t x) {
    uint32_t y;
    asm("ex2.approx.f16x2 %0, %1;" : "=r"(y) : "r"(x));
    return y;
}

__device__ __forceinline__ uint32_t pack_h2(float a, float b) {
    __half2 p = __floats2half2_rn(a, b);
    return *(uint32_t*)&p;
}

// ---------------------------------------------------------------------------
// Fused conversions (ONE launch):
//  blocks [0, NB_X)                : x fp32 -> fp16 flat
//  blocks [NB_X, NB_X+NB_WA)       : w_attn [K][3C] -> transposed fp16 [3C][K]
//  blocks [NB_X+NB_WA, total)      : w_proj [K][C]  -> transposed fp16 [C][K]
// ---------------------------------------------------------------------------
#define NB_X   (MROWS * CC / 4 / 256)          // 8192
#define NB_WA  ((THREECC / 32) * (CC / 32))    // 3072
#define NB_WP  ((CC / 32) * (CC / 32))         // 1024

__global__ __launch_bounds__(256) void k_convert_all(
    const float* __restrict__ x, const float* __restrict__ wa,
    const float* __restrict__ wp,
    __half* __restrict__ xh, __half* __restrict__ wah, __half* __restrict__ wph)
{
    const int bid = blockIdx.x;
    if (bid < NB_X) {
        const int i = bid * 256 + threadIdx.x;
        const float4 v = ((const float4*)x)[i];
        ((uint2*)xh)[i] = make_uint2(pack_h2(v.x, v.y), pack_h2(v.z, v.w));
        return;
    }
    // transpose path
    __shared__ float t[32][33];
    const float* s;
    __half* d;
    int K, N, nb, lb;
    if (bid < NB_X + NB_WA) {
        s = wa; d = wah; K = CC; N = THREECC; lb = bid - NB_X; nb = THREECC / 32;
    } else {
        s = wp; d = wph; K = CC; N = CC;      lb = bid - NB_X - NB_WA; nb = CC / 32;
    }
    const int n0 = (lb % nb) * 32, k0 = (lb / nb) * 32;
    const int tx = threadIdx.x & 31, ty = threadIdx.x >> 5;
    #pragma unroll
    for (int j = ty; j < 32; j += 8)
        t[j][tx] = s[(size_t)(k0 + j) * N + n0 + tx];
    __syncthreads();
    #pragma unroll
    for (int j = ty; j < 32; j += 8)
        d[(size_t)(n0 + j) * K + k0 + tx] = __float2half_rn(t[tx][j]);
}

// ---------------------------------------------------------------------------
// fp16 tensor-core GEMM: C = A[M][K] @ Bt[N][K]^T + bias
// CTA tile 128(M) x 64(N), BK=64, 256 thr = 8 warps, warp tile 64x16.
// acc = 32 regs/thread -> ~75 regs -> 3 CTAs/SM = 24 warps (the untested
// occupancy point). 2-stage pipeline, 55.3KB smem/CTA (3x = 166KB).
// ---------------------------------------------------------------------------
#define OFF_A  0
#define OFF_B  18432                    // A: 128x144
#define STAGE_BYTES (18432 + 9216)      // + B: 64x144 = 27648
#define GEMM_SMEM (2 * STAGE_BYTES)     // 55296

__global__ __launch_bounds__(256, 3) void tc_gemm(
    int Ndim,
    const __half* __restrict__ Ah, const __half* __restrict__ Bh,
    const float* __restrict__ bias, float* __restrict__ Cf,
    __half* __restrict__ Ch, int planes)
{
    extern __shared__ __align__(128) unsigned char smraw[];
    const uint32_t sb0 = smem_u32(smraw);
    const int tid = threadIdx.x, lane = tid & 31, wid = tid >> 5;
    const int m0 = blockIdx.y * 128, n0 = blockIdx.x * 64;
    const int wm = (wid >> 2) * 64, wn = (wid & 3) * 16;

    const __half* gA = Ah + (size_t)m0 * KD;
    const __half* gB = Bh + (size_t)n0 * KD;

    auto issue = [&](int stage, int kc) {
        const int k0 = kc * 64;
        const uint32_t sb = sb0 + stage * STAGE_BYTES;
        #pragma unroll
        for (int j = 0; j < 6; j++) {               // 192 rows x 8 chunks / 256
            const int c = j * 256 + tid;
            const int row = c >> 3, ch = c & 7;
            if (row < 128) {
                cp16(sb + OFF_A + (uint32_t)(row * 144 + ch * 16),
                     gA + (size_t)row * KD + k0 + ch * 8);
            } else {
                const int r2 = row - 128;
                cp16(sb + OFF_B + (uint32_t)(r2 * 144 + ch * 16),
                     gB + (size_t)r2 * KD + k0 + ch * 8);
            }
        }
    };

    issue(0, 0); CP_COMMIT();
    issue(1, 1); CP_COMMIT();

    float acc[4][2][4] = {};

    const uint32_t aRowOff  = (uint32_t)((wm + (lane & 15)) * 144);
    const uint32_t aColHalf = (uint32_t)((lane >> 4) * 16);
    const uint32_t bRowOff  = (uint32_t)((wn + (lane >> 4) * 8 + (lane & 7)) * 144);
    const uint32_t bColHalf = (uint32_t)(((lane >> 3) & 1) * 16);

    for (int c = 0; c < 16; c++) {
        CP_WAIT(1);
        __syncthreads();

        const uint32_t sb = sb0 + (c & 1) * STAGE_BYTES;
        #pragma unroll
        for (int ks = 0; ks < 4; ks++) {
            uint32_t af[4][4], bf[4];
            const uint32_t acol = (uint32_t)(ks * 32) + aColHalf;
            const uint32_t bcol = (uint32_t)(ks * 32) + bColHalf;
            #pragma unroll
            for (int mt = 0; mt < 4; mt++)
                ldm_x4(af[mt], sb + OFF_A + aRowOff + (uint32_t)(mt * 16 * 144) + acol);
            ldm_x4(bf, sb + OFF_B + bRowOff + bcol);
            #pragma unroll
            for (int mt = 0; mt < 4; mt++) {
                MMA_F16(acc[mt][0], af[mt], bf[0], bf[1]);
                MMA_F16(acc[mt][1], af[mt], bf[2], bf[3]);
            }
        }
        __syncthreads();
        if (c + 2 < 16) issue(c & 1, c + 2);
        CP_COMMIT();
    }

    const int er = m0 + wm + (lane >> 2);
    const int ec = n0 + wn + (lane & 3) * 2;
    #pragma unroll
    for (int mt = 0; mt < 4; mt++) {
        #pragma unroll
        for (int nt = 0; nt < 2; nt++) {
            const int r = er + mt * 16;
            const int cn = ec + nt * 8;
            const float b0 = bias[cn], b1 = bias[cn + 1];
            const float v0 = acc[mt][nt][0] + b0, v1 = acc[mt][nt][1] + b1;
            const float v2 = acc[mt][nt][2] + b0, v3 = acc[mt][nt][3] + b1;
            if (!planes) {
                *(float2*)(Cf + (size_t)r * Ndim + cn) = make_float2(v0, v1);
                *(float2*)(Cf + (size_t)(r + 8) * Ndim + cn) = make_float2(v2, v3);
            } else {
                *(uint32_t*)(Ch + (size_t)r * Ndim + cn)       = pack_h2(v0, v1);
                *(uint32_t*)(Ch + (size_t)(r + 8) * Ndim + cn) = pack_h2(v2, v3);
            }
        }
    }
}

// ---------------------------------------------------------------------------
// fp16 causal flash attention (R15: 64-key tiles, 3-stage single-sync ring).
// CTA = 128 threads x 64 queries; 4 CTAs/SM.
// ---------------------------------------------------------------------------
#define KV_STAGE 18432
#define FLASH_SMEM (3 * KV_STAGE)   // 55296

__global__ __launch_bounds__(128, 4) void flash_tc()
{
    extern __shared__ __align__(128) unsigned char fsm[];
    const uint32_t OKV = smem_u32(fsm);
    const int tid = threadIdx.x, lane = tid & 31, wid = tid >> 5;
    const int qt = (int)(gridDim.x - 1 - blockIdx.x);   // heavy CTAs first
    const int b = blockIdx.y >> 4, h = blockIdx.y & 15;
    const int q0 = qt * 64, wm = wid * 16;
    const size_t rowB = (size_t)b * TT;
    const int h64 = h * 64;
    const int NT = qt + 1;

    auto issueQ = [&]() {
        #pragma unroll
        for (int j = 0; j < 4; j++) {
            const int c = j * 128 + tid;
            const int row = c >> 3, ch = c & 7;
            const __half* src = g_qkvh + (rowB + q0 + row) * THREECC + h64 + ch * 8;
            cp16(OKV + row * 144 + ch * 16, src);
        }
    };
    auto issueKV = [&](int st, int tt) {
        const int j0 = tt * 64;
        const uint32_t sb = OKV + st * KV_STAGE;
        #pragma unroll
        for (int j = 0; j < 8; j++) {
            const int c = j * 128 + tid;
            const int pl = c >> 9, row = (c >> 3) & 63, ch = c & 7;
            const __half* src = g_qkvh
                + (rowB + j0 + row) * THREECC + (pl ? 2 * CC : CC) + h64 + ch * 8;
            cp16(sb + pl * 9216 + row * 144 + ch * 16, src);
        }
    };

    const uint32_t koff = (uint32_t)(((((lane >> 4) & 1) * 8 + (lane & 7)) * 144)
                                     + ((lane >> 3) & 1) * 16);
    const uint32_t voff = (uint32_t)(((((lane >> 3) & 1) * 8 + (lane & 7)) * 144)
                                     + ((lane >> 4) & 1) * 16);
    const uint32_t qoff = (uint32_t)(((wm + ((lane >> 3) & 1) * 8 + (lane & 7)) * 144)
                                     + ((lane >> 4) & 1) * 16);

    issueQ(); CP_COMMIT();
    CP_WAIT(0);
    __syncthreads();
    uint32_t qhf[4][4];
    #pragma unroll
    for (int ks = 0; ks < 4; ks++)
        ldm_x4(qhf[ks], OKV + qoff + ks * 32);
    __syncthreads();

    issueKV(0, 0); CP_COMMIT();
    if (NT > 1) issueKV(1, 1);
    CP_COMMIT();

    float m0r = -1e30f, m1r = -1e30f, l0r = 0.f, l1r = 0.f;
    float o[8][4] = {};
    const float SC = 0.125f * 1.4426950408889634f;
    const int rq0 = q0 + wm + (lane >> 2);
    const int colb = (lane & 3) * 2;
    const uint32_t ONE2 = 0x3C003C00u;

    int stgC = 0, stgI = 2;
    for (int t = 0; t < NT; t++) {
        CP_WAIT(1);
        __syncthreads();
        if (t + 2 < NT) issueKV(stgI, t + 2);
        CP_COMMIT();

        const uint32_t sb = OKV + stgC * KV_STAGE;
        const uint32_t KH = sb, VH = sb + 9216;
        const int j0 = t * 64;

        float s[8][4] = {};
        #pragma unroll
        for (int ks = 0; ks < 4; ks++) {
            uint32_t kh[4][4];
            #pragma unroll
            for (int g = 0; g < 4; g++)
                ldm_x4(kh[g], KH + g * 2304 + ks * 32 + koff);
            #pragma unroll
            for (int g = 0; g < 4; g++) {
                MMA_F16(s[2*g],   qhf[ks], kh[g][0], kh[g][1]);
                MMA_F16(s[2*g+1], qhf[ks], kh[g][2], kh[g][3]);
            }
        }

        if (t == qt) {
            #pragma unroll
            for (int nt = 0; nt < 8; nt++) {
                const int c0 = j0 + nt * 8 + colb;
                #pragma unroll
                for (int j = 0; j < 4; j++) {
                    const int cg = c0 + (j & 1);
                    const int rg = rq0 + ((j >> 1) << 3);
                    s[nt][j] = (cg <= rg) ? s[nt][j] * SC : -1e30f;
                }
            }
        } else {
            #pragma unroll
            for (int nt = 0; nt < 8; nt++)
                #pragma unroll
                for (int j = 0; j < 4; j++) s[nt][j] *= SC;
        }

        float mx0 = -1e30f, mx1 = -1e30f;
        #pragma unroll
        for (int nt = 0; nt < 8; nt++) {
            mx0 = fmaxf(mx0, fmaxf(s[nt][0], s[nt][1]));
            mx1 = fmaxf(mx1, fmaxf(s[nt][2], s[nt][3]));
        }
        mx0 = fmaxf(mx0, __shfl_xor_sync(0xffffffffu, mx0, 1));
        mx0 = fmaxf(mx0, __shfl_xor_sync(0xffffffffu, mx0, 2));
        mx1 = fmaxf(mx1, __shfl_xor_sync(0xffffffffu, mx1, 1));
        mx1 = fmaxf(mx1, __shfl_xor_sync(0xffffffffu, mx1, 2));
        const float mn0 = fmaxf(m0r, mx0), mn1 = fmaxf(m1r, mx1);
        const float a0 = ex2f(m0r - mn0), a1 = ex2f(m1r - mn1);
        m0r = mn0; m1r = mn1;

        uint32_t ph[4][4];
        #pragma unroll
        for (int kt = 0; kt < 4; kt++) {
            ph[kt][0] = ex2_h2(pack_h2(s[2*kt][0]   - mn0, s[2*kt][1]   - mn0));
            ph[kt][1] = ex2_h2(pack_h2(s[2*kt][2]   - mn1, s[2*kt][3]   - mn1));
            ph[kt][2] = ex2_h2(pack_h2(s[2*kt+1][0] - mn0, s[2*kt+1][1] - mn0));
            ph[kt][3] = ex2_h2(pack_h2(s[2*kt+1][2] - mn1, s[2*kt+1][3] - mn1));
        }

        float racc[4] = {0.f, 0.f, 0.f, 0.f};
        #pragma unroll
        for (int kt = 0; kt < 4; kt++)
            MMA_F16(racc, ph[kt], ONE2, ONE2);
        l0r = l0r * a0 + racc[0];
        l1r = l1r * a1 + racc[2];

        #pragma unroll
        for (int nt = 0; nt < 8; nt++) {
            o[nt][0] *= a0; o[nt][1] *= a0;
            o[nt][2] *= a1; o[nt][3] *= a1;
        }

        #pragma unroll
        for (int kt = 0; kt < 4; kt++) {
            uint32_t vh[4][4];
            #pragma unroll
            for (int g = 0; g < 4; g++)
                ldm_x4t(vh[g], VH + kt * 2304 + g * 32 + voff);
            #pragma unroll
            for (int g = 0; g < 4; g++) {
                MMA_F16(o[2*g],   ph[kt], vh[g][0], vh[g][1]);
                MMA_F16(o[2*g+1], ph[kt], vh[g][2], vh[g][3]);
            }
        }

        stgC = (stgC == 2) ? 0 : stgC + 1;
        stgI = (stgI == 2) ? 0 : stgI + 1;
    }

    const float i0 = 1.0f / l0r, i1 = 1.0f / l1r;
    const size_t r0 = rowB + (size_t)rq0;
    #pragma unroll
    for (int nt = 0; nt < 8; nt++) {
        const int col = h64 + nt * 8 + colb;
        *(uint32_t*)(g_ah + r0 * CC + col)       = pack_h2(o[nt][0] * i0, o[nt][1] * i0);
        *(uint32_t*)(g_ah + (r0 + 8) * CC + col) = pack_h2(o[nt][2] * i1, o[nt][3] * i1);
    }
}

// ---------------------------------------------------------------------------
extern "C" void kernel_launch(void* const* d_in, const int* in_sizes, int n_in,
                              void* d_out, int out_size)
{
    const float* x      = (const float*)d_in[0];
    const float* w_attn = (const float*)d_in[1];
    const float* b_attn = (const float*)d_in[2];
    const float* w_proj = (const float*)d_in[3];
    const float* b_proj = (const float*)d_in[4];
    float* out = (float*)d_out;

    __half *qkvh, *xh, *wah, *wph, *ah;
    cudaGetSymbolAddress((void**)&qkvh, g_qkvh);
    cudaGetSymbolAddress((void**)&xh, g_xh);
    cudaGetSymbolAddress((void**)&wah, g_wah);
    cudaGetSymbolAddress((void**)&wph, g_wph);
    cudaGetSymbolAddress((void**)&ah, g_ah);

    cudaFuncSetAttribute(tc_gemm,
                         cudaFuncAttributeMaxDynamicSharedMemorySize, GEMM_SMEM);
    cudaFuncSetAttribute(flash_tc,
                         cudaFuncAttributeMaxDynamicSharedMemorySize, FLASH_SMEM);

    // 0) fused input conversions (one launch)
    k_convert_all<<<NB_X + NB_WA + NB_WP, 256>>>(x, w_attn, w_proj, xh, wah, wph);

    // 1) qkv = fp16(xh @ w_attn^T + b_attn)   grid 48 x 64 (N-tile 64)
    tc_gemm<<<dim3(THREECC / 64, MROWS / 128), 256, GEMM_SMEM>>>(
        THREECC, xh, wah, b_attn, nullptr, qkvh, 1);

    // 2) fp16 causal flash attention -> g_ah
    flash_tc<<<dim3(TT / 64, BB * NH), 128, FLASH_SMEM>>>();

    // 3) out = ah @ w_proj^T + b_proj (fp32)  grid 16 x 64
    tc_gemm<<<dim3(CC / 64, MROWS / 128), 256, GEMM_SMEM>>>(
        CC, ah, wph, b_proj, out, nullptr, 0);
}

// round 17
// speedup vs baseline: 1.1081x; 1.1081x over previous
#include <cuda_runtime.h>
#include <cuda_fp16.h>
#include <cstdint>
#include <math.h>

// Problem constants
#define BB 4
#define TT 2048
#define CC 1024
#define NH 16
#define HSZ 64
#define MROWS (BB*TT)        // 8192
#define THREECC (3*CC)       // 3072
#define KD 1024

// ---------------------------------------------------------------------------
// Global scratch (device globals: allocation-free). fp16 hi planes only.
// ---------------------------------------------------------------------------
__device__ __half g_qkvh[(size_t)MROWS * THREECC];  // qkv
__device__ __half g_xh[(size_t)MROWS * CC];         // x [M][K]
__device__ __half g_wah[(size_t)THREECC * CC];      // w_attn^T [N][K]
__device__ __half g_wph[(size_t)CC * CC];           // w_proj^T [N][K]
__device__ __half g_ah[(size_t)MROWS * CC];         // attn out

// ---------------------------------------------------------------------------
// Helpers
// ---------------------------------------------------------------------------
__device__ __forceinline__ uint32_t smem_u32(const void* p) {
    uint32_t a;
    asm("{ .reg .u64 t; cvta.to.shared.u64 t, %1; cvt.u32.u64 %0, t; }"
        : "=r"(a) : "l"(p));
    return a;
}

__device__ __forceinline__ void cp16(uint32_t dst, const void* src) {
    asm volatile("cp.async.cg.shared.global [%0], [%1], 16;"
                 :: "r"(dst), "l"(src));
}
#define CP_COMMIT() asm volatile("cp.async.commit_group;" ::: "memory")
#define CP_WAIT(n)  asm volatile("cp.async.wait_group %0;" :: "n"(n) : "memory")

__device__ __forceinline__ void ldm_x4(uint32_t* r, uint32_t addr) {
    asm volatile("ldmatrix.sync.aligned.m8n8.x4.shared.b16 {%0,%1,%2,%3}, [%4];"
                 : "=r"(r[0]), "=r"(r[1]), "=r"(r[2]), "=r"(r[3]) : "r"(addr));
}
__device__ __forceinline__ void ldm_x4t(uint32_t* r, uint32_t addr) {
    asm volatile("ldmatrix.sync.aligned.m8n8.x4.trans.shared.b16 {%0,%1,%2,%3}, [%4];"
                 : "=r"(r[0]), "=r"(r[1]), "=r"(r[2]), "=r"(r[3]) : "r"(addr));
}

#define MMA_F16(acc, a, b0, b1)                                               \
    asm volatile(                                                             \
        "mma.sync.aligned.m16n8k16.row.col.f32.f16.f16.f32 "                  \
        "{%0,%1,%2,%3},{%4,%5,%6,%7},{%8,%9},{%0,%1,%2,%3};"                  \
        : "+f"((acc)[0]), "+f"((acc)[1]), "+f"((acc)[2]), "+f"((acc)[3])      \
        : "r"((a)[0]), "r"((a)[1]), "r"((a)[2]), "r"((a)[3]),                 \
          "r"(b0), "r"(b1))

__device__ __forceinline__ float ex2f(float x) {
    float y;
    asm("ex2.approx.f32 %0, %1;" : "=f"(y) : "f"(x));
    return y;
}

__device__ __forceinline__ uint32_t ex2_h2(uint32_t x) {
    uint32_t y;
    asm("ex2.approx.f16x2 %0, %1;" : "=r"(y) : "r"(x));
    return y;
}

__device__ __forceinline__ uint32_t pack_h2(float a, float b) {
    __half2 p = __floats2half2_rn(a, b);
    return *(uint32_t*)&p;
}

// ---------------------------------------------------------------------------
// Fused conversions (ONE launch):
//  blocks [0, NB_X)                : x fp32 -> fp16 flat
//  blocks [NB_X, NB_X+NB_WA)       : w_attn [K][3C] -> transposed fp16 [3C][K]
//  blocks [NB_X+NB_WA, total)      : w_proj [K][C]  -> transposed fp16 [C][K]
// ---------------------------------------------------------------------------
#define NB_X   (MROWS * CC / 4 / 256)          // 8192
#define NB_WA  ((THREECC / 32) * (CC / 32))    // 3072
#define NB_WP  ((CC / 32) * (CC / 32))         // 1024

__global__ __launch_bounds__(256) void k_convert_all(
    const float* __restrict__ x, const float* __restrict__ wa,
    const float* __restrict__ wp,
    __half* __restrict__ xh, __half* __restrict__ wah, __half* __restrict__ wph)
{
    const int bid = blockIdx.x;
    if (bid < NB_X) {
        const int i = bid * 256 + threadIdx.x;
        const float4 v = ((const float4*)x)[i];
        ((uint2*)xh)[i] = make_uint2(pack_h2(v.x, v.y), pack_h2(v.z, v.w));
        return;
    }
    __shared__ float t[32][33];
    const float* s;
    __half* d;
    int K, N, nb, lb;
    if (bid < NB_X + NB_WA) {
        s = wa; d = wah; K = CC; N = THREECC; lb = bid - NB_X; nb = THREECC / 32;
    } else {
        s = wp; d = wph; K = CC; N = CC;      lb = bid - NB_X - NB_WA; nb = CC / 32;
    }
    const int n0 = (lb % nb) * 32, k0 = (lb / nb) * 32;
    const int tx = threadIdx.x & 31, ty = threadIdx.x >> 5;
    #pragma unroll
    for (int j = ty; j < 32; j += 8)
        t[j][tx] = s[(size_t)(k0 + j) * N + n0 + tx];
    __syncthreads();
    #pragma unroll
    for (int j = ty; j < 32; j += 8)
        d[(size_t)(n0 + j) * K + k0 + tx] = __float2half_rn(t[tx][j]);
}

// ---------------------------------------------------------------------------
// fp16 tensor-core GEMM (R15 config — best measured): C = A @ Bt^T + bias
// 128x128 CTA tile, BK=64, 256 thr, warp tile 64x32, 3-stage ring with a
// single sync per chunk (issue chunk c+2 into the just-vacated buffer).
// 2 CTAs/SM = 16 warps.
// ---------------------------------------------------------------------------
#define STAGE_BYTES (2 * 18432)   // 36864
#define OFF_A  0
#define OFF_B  18432
#define GEMM_SMEM (3 * STAGE_BYTES)   // 110592

__global__ __launch_bounds__(256, 2) void tc_gemm(
    int Ndim,
    const __half* __restrict__ Ah, const __half* __restrict__ Bh,
    const float* __restrict__ bias, float* __restrict__ Cf,
    __half* __restrict__ Ch, int planes)
{
    extern __shared__ __align__(128) unsigned char smraw[];
    const uint32_t sb0 = smem_u32(smraw);
    const int tid = threadIdx.x, lane = tid & 31, wid = tid >> 5;
    const int m0 = blockIdx.y * 128, n0 = blockIdx.x * 128;
    const int wm = (wid >> 2) * 64, wn = (wid & 3) * 32;

    const __half* gA = Ah + (size_t)m0 * KD;
    const __half* gB = Bh + (size_t)n0 * KD;

    auto issue = [&](int stage, int kc) {
        const int k0 = kc * 64;
        const uint32_t sb = sb0 + stage * STAGE_BYTES;
        #pragma unroll
        for (int j = 0; j < 4; j++) {
            const int c = j * 256 + tid;
            const int row = c >> 3, ch = c & 7;
            const uint32_t d = (uint32_t)(row * 144 + ch * 16);
            const size_t g = (size_t)row * KD + k0 + ch * 8;
            cp16(sb + OFF_A + d, gA + g);
            cp16(sb + OFF_B + d, gB + g);
        }
    };

    issue(0, 0); CP_COMMIT();
    issue(1, 1); CP_COMMIT();

    float acc[4][4][4] = {};

    const uint32_t aRowOff  = (uint32_t)((wm + (lane & 15)) * 144);
    const uint32_t aColHalf = (uint32_t)((lane >> 4) * 16);
    const uint32_t bRowOff  = (uint32_t)((wn + (lane >> 4) * 8 + (lane & 7)) * 144);
    const uint32_t bColHalf = (uint32_t)(((lane >> 3) & 1) * 16);

    int stgC = 0;   // buffer of chunk c
    int stgI = 2;   // buffer for chunk c+2
    for (int c = 0; c < 16; c++) {
        CP_WAIT(1);
        __syncthreads();
        if (c + 2 < 16) issue(stgI, c + 2);
        CP_COMMIT();

        const uint32_t sb = sb0 + stgC * STAGE_BYTES;
        #pragma unroll
        for (int ks = 0; ks < 4; ks++) {
            uint32_t af[4][4], bf[2][4];
            const uint32_t acol = (uint32_t)(ks * 32) + aColHalf;
            const uint32_t bcol = (uint32_t)(ks * 32) + bColHalf;
            #pragma unroll
            for (int mt = 0; mt < 4; mt++)
                ldm_x4(af[mt], sb + OFF_A + aRowOff + (uint32_t)(mt * 16 * 144) + acol);
            #pragma unroll
            for (int p = 0; p < 2; p++)
                ldm_x4(bf[p], sb + OFF_B + bRowOff + (uint32_t)(p * 16 * 144) + bcol);
            #pragma unroll
            for (int mt = 0; mt < 4; mt++)
                #pragma unroll
                for (int nt = 0; nt < 4; nt++) {
                    const uint32_t* bp = &bf[nt >> 1][(nt & 1) * 2];
                    MMA_F16(acc[mt][nt], af[mt], bp[0], bp[1]);
                }
        }
        stgC = (stgC == 2) ? 0 : stgC + 1;
        stgI = (stgI == 2) ? 0 : stgI + 1;
    }

    const int er = m0 + wm + (lane >> 2);
    const int ec = n0 + wn + (lane & 3) * 2;
    #pragma unroll
    for (int mt = 0; mt < 4; mt++) {
        #pragma unroll
        for (int nt = 0; nt < 4; nt++) {
            const int r = er + mt * 16;
            const int cn = ec + nt * 8;
            const float b0 = bias[cn], b1 = bias[cn + 1];
            const float v0 = acc[mt][nt][0] + b0, v1 = acc[mt][nt][1] + b1;
            const float v2 = acc[mt][nt][2] + b0, v3 = acc[mt][nt][3] + b1;
            if (!planes) {
                *(float2*)(Cf + (size_t)r * Ndim + cn) = make_float2(v0, v1);
                *(float2*)(Cf + (size_t)(r + 8) * Ndim + cn) = make_float2(v2, v3);
            } else {
                *(uint32_t*)(Ch + (size_t)r * Ndim + cn)       = pack_h2(v0, v1);
                *(uint32_t*)(Ch + (size_t)(r + 8) * Ndim + cn) = pack_h2(v2, v3);
            }
        }
    }
}

// ---------------------------------------------------------------------------
// fp16 causal flash attention (R15 config — best measured):
// 64-key tiles, 3-stage KV ring, single sync per tile.
// CTA = 128 threads x 64 queries; 55.3KB smem -> 4 CTAs/SM.
// ---------------------------------------------------------------------------
#define KV_STAGE 18432
#define FLASH_SMEM (3 * KV_STAGE)   // 55296

__global__ __launch_bounds__(128, 4) void flash_tc()
{
    extern __shared__ __align__(128) unsigned char fsm[];
    const uint32_t OKV = smem_u32(fsm);
    const int tid = threadIdx.x, lane = tid & 31, wid = tid >> 5;
    const int qt = (int)(gridDim.x - 1 - blockIdx.x);   // heavy CTAs first
    const int b = blockIdx.y >> 4, h = blockIdx.y & 15;
    const int q0 = qt * 64, wm = wid * 16;
    const size_t rowB = (size_t)b * TT;
    const int h64 = h * 64;
    const int NT = qt + 1;

    auto issueQ = [&]() {
        #pragma unroll
        for (int j = 0; j < 4; j++) {
            const int c = j * 128 + tid;
            const int row = c >> 3, ch = c & 7;
            const __half* src = g_qkvh + (rowB + q0 + row) * THREECC + h64 + ch * 8;
            cp16(OKV + row * 144 + ch * 16, src);
        }
    };
    auto issueKV = [&](int st, int tt) {
        const int j0 = tt * 64;
        const uint32_t sb = OKV + st * KV_STAGE;
        #pragma unroll
        for (int j = 0; j < 8; j++) {
            const int c = j * 128 + tid;
            const int pl = c >> 9, row = (c >> 3) & 63, ch = c & 7;
            const __half* src = g_qkvh
                + (rowB + j0 + row) * THREECC + (pl ? 2 * CC : CC) + h64 + ch * 8;
            cp16(sb + pl * 9216 + row * 144 + ch * 16, src);
        }
    };

    const uint32_t koff = (uint32_t)(((((lane >> 4) & 1) * 8 + (lane & 7)) * 144)
                                     + ((lane >> 3) & 1) * 16);
    const uint32_t voff = (uint32_t)(((((lane >> 3) & 1) * 8 + (lane & 7)) * 144)
                                     + ((lane >> 4) & 1) * 16);
    const uint32_t qoff = (uint32_t)(((wm + ((lane >> 3) & 1) * 8 + (lane & 7)) * 144)
                                     + ((lane >> 4) & 1) * 16);

    issueQ(); CP_COMMIT();
    CP_WAIT(0);
    __syncthreads();
    uint32_t qhf[4][4];
    #pragma unroll
    for (int ks = 0; ks < 4; ks++)
        ldm_x4(qhf[ks], OKV + qoff + ks * 32);
    __syncthreads();

    issueKV(0, 0); CP_COMMIT();
    if (NT > 1) issueKV(1, 1);
    CP_COMMIT();

    float m0r = -1e30f, m1r = -1e30f, l0r = 0.f, l1r = 0.f;
    float o[8][4] = {};
    const float SC = 0.125f * 1.4426950408889634f;
    const int rq0 = q0 + wm + (lane >> 2);
    const int colb = (lane & 3) * 2;
    const uint32_t ONE2 = 0x3C003C00u;

    int stgC = 0, stgI = 2;
    for (int t = 0; t < NT; t++) {
        CP_WAIT(1);
        __syncthreads();
        if (t + 2 < NT) issueKV(stgI, t + 2);
        CP_COMMIT();

        const uint32_t sb = OKV + stgC * KV_STAGE;
        const uint32_t KH = sb, VH = sb + 9216;
        const int j0 = t * 64;

        float s[8][4] = {};
        #pragma unroll
        for (int ks = 0; ks < 4; ks++) {
            uint32_t kh[4][4];
            #pragma unroll
            for (int g = 0; g < 4; g++)
                ldm_x4(kh[g], KH + g * 2304 + ks * 32 + koff);
            #pragma unroll
            for (int g = 0; g < 4; g++) {
                MMA_F16(s[2*g],   qhf[ks], kh[g][0], kh[g][1]);
                MMA_F16(s[2*g+1], qhf[ks], kh[g][2], kh[g][3]);
            }
        }

        if (t == qt) {
            #pragma unroll
            for (int nt = 0; nt < 8; nt++) {
                const int c0 = j0 + nt * 8 + colb;
                #pragma unroll
                for (int j = 0; j < 4; j++) {
                    const int cg = c0 + (j & 1);
                    const int rg = rq0 + ((j >> 1) << 3);
                    s[nt][j] = (cg <= rg) ? s[nt][j] * SC : -1e30f;
                }
            }
        } else {
            #pragma unroll
            for (int nt = 0; nt < 8; nt++)
                #pragma unroll
                for (int j = 0; j < 4; j++) s[nt][j] *= SC;
        }

        float mx0 = -1e30f, mx1 = -1e30f;
        #pragma unroll
        for (int nt = 0; nt < 8; nt++) {
            mx0 = fmaxf(mx0, fmaxf(s[nt][0], s[nt][1]));
            mx1 = fmaxf(mx1, fmaxf(s[nt][2], s[nt][3]));
        }
        mx0 = fmaxf(mx0, __shfl_xor_sync(0xffffffffu, mx0, 1));
        mx0 = fmaxf(mx0, __shfl_xor_sync(0xffffffffu, mx0, 2));
        mx1 = fmaxf(mx1, __shfl_xor_sync(0xffffffffu, mx1, 1));
        mx1 = fmaxf(mx1, __shfl_xor_sync(0xffffffffu, mx1, 2));
        const float mn0 = fmaxf(m0r, mx0), mn1 = fmaxf(m1r, mx1);
        const float a0 = ex2f(m0r - mn0), a1 = ex2f(m1r - mn1);
        m0r = mn0; m1r = mn1;

        uint32_t ph[4][4];
        #pragma unroll
        for (int kt = 0; kt < 4; kt++) {
            ph[kt][0] = ex2_h2(pack_h2(s[2*kt][0]   - mn0, s[2*kt][1]   - mn0));
            ph[kt][1] = ex2_h2(pack_h2(s[2*kt][2]   - mn1, s[2*kt][3]   - mn1));
            ph[kt][2] = ex2_h2(pack_h2(s[2*kt+1][0] - mn0, s[2*kt+1][1] - mn0));
            ph[kt][3] = ex2_h2(pack_h2(s[2*kt+1][2] - mn1, s[2*kt+1][3] - mn1));
        }

        float racc[4] = {0.f, 0.f, 0.f, 0.f};
        #pragma unroll
        for (int kt = 0; kt < 4; kt++)
            MMA_F16(racc, ph[kt], ONE2, ONE2);
        l0r = l0r * a0 + racc[0];
        l1r = l1r * a1 + racc[2];

        #pragma unroll
        for (int nt = 0; nt < 8; nt++) {
            o[nt][0] *= a0; o[nt][1] *= a0;
            o[nt][2] *= a1; o[nt][3] *= a1;
        }

        #pragma unroll
        for (int kt = 0; kt < 4; kt++) {
            uint32_t vh[4][4];
            #pragma unroll
            for (int g = 0; g < 4; g++)
                ldm_x4t(vh[g], VH + kt * 2304 + g * 32 + voff);
            #pragma unroll
            for (int g = 0; g < 4; g++) {
                MMA_F16(o[2*g],   ph[kt], vh[g][0], vh[g][1]);
                MMA_F16(o[2*g+1], ph[kt], vh[g][2], vh[g][3]);
            }
        }

        stgC = (stgC == 2) ? 0 : stgC + 1;
        stgI = (stgI == 2) ? 0 : stgI + 1;
    }

    const float i0 = 1.0f / l0r, i1 = 1.0f / l1r;
    const size_t r0 = rowB + (size_t)rq0;
    #pragma unroll
    for (int nt = 0; nt < 8; nt++) {
        const int col = h64 + nt * 8 + colb;
        *(uint32_t*)(g_ah + r0 * CC + col)       = pack_h2(o[nt][0] * i0, o[nt][1] * i0);
        *(uint32_t*)(g_ah + (r0 + 8) * CC + col) = pack_h2(o[nt][2] * i1, o[nt][3] * i1);
    }
}

// ---------------------------------------------------------------------------
extern "C" void kernel_launch(void* const* d_in, const int* in_sizes, int n_in,
                              void* d_out, int out_size)
{
    const float* x      = (const float*)d_in[0];
    const float* w_attn = (const float*)d_in[1];
    const float* b_attn = (const float*)d_in[2];
    const float* w_proj = (const float*)d_in[3];
    const float* b_proj = (const float*)d_in[4];
    float* out = (float*)d_out;

    __half *qkvh, *xh, *wah, *wph, *ah;
    cudaGetSymbolAddress((void**)&qkvh, g_qkvh);
    cudaGetSymbolAddress((void**)&xh, g_xh);
    cudaGetSymbolAddress((void**)&wah, g_wah);
    cudaGetSymbolAddress((void**)&wph, g_wph);
    cudaGetSymbolAddress((void**)&ah, g_ah);

    cudaFuncSetAttribute(tc_gemm,
                         cudaFuncAttributeMaxDynamicSharedMemorySize, GEMM_SMEM);
    cudaFuncSetAttribute(flash_tc,
                         cudaFuncAttributeMaxDynamicSharedMemorySize, FLASH_SMEM);

    // 0) fused input conversions (one launch)
    k_convert_all<<<NB_X + NB_WA + NB_WP, 256>>>(x, w_attn, w_proj, xh, wah, wph);

    // 1) qkv = fp16(xh @ w_attn^T + b_attn)
    tc_gemm<<<dim3(THREECC / 128, MROWS / 128), 256, GEMM_SMEM>>>(
        THREECC, xh, wah, b_attn, nullptr, qkvh, 1);

    // 2) fp16 causal flash attention -> g_ah
    flash_tc<<<dim3(TT / 64, BB * NH), 128, FLASH_SMEM>>>();

    // 3) out = ah @ w_proj^T + b_proj (fp32)
    tc_gemm<<<dim3(CC / 128, MROWS / 128), 256, GEMM_SMEM>>>(
        CC, ah, wph, b_proj, out, nullptr, 0);
}